// round 13
// baseline (speedup 1.0000x reference)
#include <cuda_runtime.h>
#include <math.h>

// Per-row least-squares ternary quantization.
// w: [4096, M=11008] fp32, skip (int, =3). Output w_q same shape.
//
// 1 block per row. Exact bitonic sort of |w| bits (16384 padded), then the
// XLA ReduceWindowRewriter(base=16) cumsum applied RECURSIVELY with trailing
// padding (the R9 association -- empirically the closest structure):
//   level0: 11008 = 688*16 -> per-16 fold-left partials P0, sums S0[688]
//   level1:   688 =  43*16 -> per-16 fold-left partials P1, sums S1[43]
//   level2:    43 -> pad high to 48 -> blocks {0-15},{16-31},{32-42}
//   base:     sequential fold-left over the 3 block sums -> exclusive E2
//   then E-combines back down (blocks with E==0 skip: fl(0+x)=x).
// SCORE = fl(fl(c*c) * rcp_rn(k)) -- the jitted-XLA form: algebraic
// simplifier rewrites divide-by-constant into multiply by the constant-folded
// (correctly rounded) reciprocal.  v1 keeps true CR division (data-dependent
// divisor cannot be const-folded).
// First-occurrence argmax, elementwise output pass.

#define M_COLS   11008
#define NPAD     16384
#define NTHREADS 1024
#define B0       688   // 11008/16
#define B1       43    // 688/16
#define B2       3     // ceil(43/16)

// dynamic smem layout:
//   u32   keys[NPAD]   : 65536 B
//   float cs[M_COLS]   : 44032 B
//   float S0[704], W1[704] (P1 -> scanS0 in place)
//   float S1[48],  W2[48]  (P2 -> scan1 in place)
//   float E2s[8]
//   float reds[32]; int redj[32]; float bc[4]
#define SMEM_KEYS_OFF  0
#define SMEM_CS_OFF    (NPAD * 4)
#define SMEM_S0_OFF    (SMEM_CS_OFF + M_COLS * 4)
#define SMEM_W1_OFF    (SMEM_S0_OFF + 704 * 4)
#define SMEM_S1_OFF    (SMEM_W1_OFF + 704 * 4)
#define SMEM_W2_OFF    (SMEM_S1_OFF + 48 * 4)
#define SMEM_E2_OFF    (SMEM_W2_OFF + 48 * 4)
#define SMEM_REDS_OFF  (SMEM_E2_OFF + 8 * 4)
#define SMEM_REDJ_OFF  (SMEM_REDS_OFF + 32 * 4)
#define SMEM_BC_OFF    (SMEM_REDJ_OFF + 32 * 4)
#define SMEM_BYTES     (SMEM_BC_OFF + 16)

__global__ __launch_bounds__(NTHREADS)
void lst_ternary_kernel(const float* __restrict__ w,
                        const int* __restrict__ skip_p,
                        float* __restrict__ out,
                        int m)
{
    extern __shared__ unsigned char smem_raw[];
    unsigned int* keys = (unsigned int*)(smem_raw + SMEM_KEYS_OFF);
    float*        cs   = (float*)(smem_raw + SMEM_CS_OFF);
    float*        S0   = (float*)(smem_raw + SMEM_S0_OFF);
    float*        W1   = (float*)(smem_raw + SMEM_W1_OFF);
    float*        S1   = (float*)(smem_raw + SMEM_S1_OFF);
    float*        W2   = (float*)(smem_raw + SMEM_W2_OFF);
    float*        E2   = (float*)(smem_raw + SMEM_E2_OFF);
    float*        reds = (float*)(smem_raw + SMEM_REDS_OFF);
    int*          redj = (int*)(smem_raw + SMEM_REDJ_OFF);
    float*        bc   = (float*)(smem_raw + SMEM_BC_OFF);

    const int tid = threadIdx.x;
    const int row = blockIdx.x;
    const float* wr  = w   + (long long)row * m;
    float*       owr = out + (long long)row * m;

    // ---- 1. load keys = bits of |w| (monotone for nonneg floats), pad zeros ----
    const float4* wr4 = (const float4*)wr;
    const int m4 = m >> 2;
    for (int i = tid; i < m4; i += NTHREADS) {
        float4 v = wr4[i];
        int b = 4 * i;
        keys[b + 0] = __float_as_uint(v.x) & 0x7fffffffu;
        keys[b + 1] = __float_as_uint(v.y) & 0x7fffffffu;
        keys[b + 2] = __float_as_uint(v.z) & 0x7fffffffu;
        keys[b + 3] = __float_as_uint(v.w) & 0x7fffffffu;
    }
    for (int i = m + tid; i < NPAD; i += NTHREADS) keys[i] = 0u;
    __syncthreads();

    // ---- 2. bitonic sort ascending over NPAD keys (exact) ----
    for (int k = 2; k <= NPAD; k <<= 1) {
        for (int j = k >> 1; j > 0; j >>= 1) {
            #pragma unroll
            for (int base = 0; base < NPAD; base += NTHREADS) {
                int i = base + tid;
                int ixj = i ^ j;
                if (ixj > i) {
                    unsigned int a = keys[i];
                    unsigned int b = keys[ixj];
                    bool up = ((i & k) == 0);
                    if ((a > b) == up) { keys[i] = b; keys[ixj] = a; }
                }
            }
            __syncthreads();
        }
    }

    // sorted ascending; descending view over the m real values (pads at front)
    #define SDESC(i) __uint_as_float(keys[NPAD - 1 - (i)])

    // ---- 3. ReduceWindowRewriter(16), recursive, trailing pad (R9 assoc) ----
    // 3a. level0 partials: per-16 fold-left over descending values
    for (int b = tid; b < B0; b += NTHREADS) {
        const int base = b * 16;
        float p = 0.0f;
        #pragma unroll
        for (int r = 0; r < 16; ++r) {
            p = __fadd_rn(p, SDESC(base + r));
            cs[base + r] = p;
        }
        S0[b] = p;
    }
    __syncthreads();
    // 3b. level1 partials over S0 (688 = 43*16 exact)
    for (int b = tid; b < B1; b += NTHREADS) {
        const int base = b * 16;
        float p = 0.0f;
        #pragma unroll
        for (int r = 0; r < 16; ++r) {
            p = __fadd_rn(p, S0[base + r]);
            W1[base + r] = p;
        }
        S1[b] = p;
    }
    __syncthreads();
    // 3c. level2 partials over S1 (43 entries, 3 blocks; last block short)
    if (tid < B2) {
        const int base = tid * 16;
        const int hi = (base + 16 < B1) ? base + 16 : B1;
        float p = 0.0f;
        for (int t = base; t < hi; ++t) {
            p = __fadd_rn(p, S1[t]);
            W2[t] = p;
        }
        if (tid == 0) E2[4] = p;            // S2[0]
        if (tid == 1) E2[5] = p;            // S2[1]
    }
    __syncthreads();
    // 3d. base-case exclusive cumsum of S2 -> E2
    if (tid == 0) {
        E2[0] = 0.0f;
        E2[1] = E2[4];                       // S2[0]
        E2[2] = __fadd_rn(E2[4], E2[5]);     // fl(S2[0]+S2[1])
    }
    __syncthreads();
    // 3e. scan1 inclusive (in place over W2): t in [16, 43)
    for (int t = 16 + tid; t < B1; t += NTHREADS)
        W2[t] = __fadd_rn(E2[t >> 4], W2[t]);
    __syncthreads();
    // 3f. scan0 inclusive (in place over W1): q in [16, 688); E1[b1]=W2[b1-1]
    for (int q = 16 + tid; q < B0; q += NTHREADS)
        W1[q] = __fadd_rn(W2[(q >> 4) - 1], W1[q]);
    __syncthreads();
    // 3g. final combine: i in [16, m); E0[b0]=W1[b0-1]
    for (int i = 16 + tid; i < m; i += NTHREADS)
        cs[i] = __fadd_rn(W1[(i >> 4) - 1], cs[i]);
    __syncthreads();

    // ---- 4. candidate scores + first-max argmax (jnp.argmax semantics) ----
    // score = fl(fl(c*c) * rcp_rn(k))  -- jitted-XLA divide-by-constant form
    const int skip = *skip_p;
    const int ncand = (m + skip - 1) / skip;

    float bs = -1.0f;
    int   bj = 0x7fffffff;
    for (int t = tid; t < ncand; t += NTHREADS) {
        const int j = t * skip;
        const float c = cs[j];
        const float kf = (float)(j + 1);
        const float sc = __fmul_rn(__fmul_rn(c, c), __frcp_rn(kf));
        if (sc > bs) { bs = sc; bj = j; }  // per-thread j increases -> first max
    }
    #pragma unroll
    for (int o = 16; o > 0; o >>= 1) {
        float os = __shfl_down_sync(0xffffffffu, bs, o);
        int   oj = __shfl_down_sync(0xffffffffu, bj, o);
        if (os > bs || (os == bs && oj < bj)) { bs = os; bj = oj; }
    }
    if ((tid & 31) == 0) { reds[tid >> 5] = bs; redj[tid >> 5] = bj; }
    __syncthreads();
    if (tid < 32) {
        bs = reds[tid]; bj = redj[tid];
        #pragma unroll
        for (int o = 16; o > 0; o >>= 1) {
            float os = __shfl_down_sync(0xffffffffu, bs, o);
            int   oj = __shfl_down_sync(0xffffffffu, bj, o);
            if (os > bs || (os == bs && oj < bj)) { bs = os; bj = oj; }
        }
        if (tid == 0) {
            const int j = bj;
            bc[0] = __fdiv_rn(cs[j], (float)(j + 1));  // v1: true CR division
            bc[1] = SDESC(j);                          // thr
        }
    }
    __syncthreads();

    // ---- 5. output: w_q = (|w| >= thr) ? copysign(v1, w) : 0 ----
    const float v1  = bc[0];
    const float thr = bc[1];
    float4* out4 = (float4*)owr;
    for (int i = tid; i < m4; i += NTHREADS) {
        float4 v = wr4[i];
        float4 o;
        o.x = (fabsf(v.x) >= thr) ? copysignf(v1, v.x) : 0.0f;
        o.y = (fabsf(v.y) >= thr) ? copysignf(v1, v.y) : 0.0f;
        o.z = (fabsf(v.z) >= thr) ? copysignf(v1, v.z) : 0.0f;
        o.w = (fabsf(v.w) >= thr) ? copysignf(v1, v.w) : 0.0f;
        out4[i] = o;
    }
    #undef SDESC
}

extern "C" void kernel_launch(void* const* d_in, const int* in_sizes, int n_in,
                              void* d_out, int out_size)
{
    const float* w      = (const float*)d_in[0];
    const int*   skip_p = (const int*)d_in[1];
    float*       out    = (float*)d_out;

    const int m    = M_COLS;
    const int rows = in_sizes[0] / m;

    cudaFuncSetAttribute(lst_ternary_kernel,
                         cudaFuncAttributeMaxDynamicSharedMemorySize,
                         SMEM_BYTES);

    lst_ternary_kernel<<<rows, NTHREADS, SMEM_BYTES>>>(w, skip_p, out, m);
}

// round 14
// speedup vs baseline: 4.5681x; 4.5681x over previous
#include <cuda_runtime.h>
#include <cub/cub.cuh>
#include <math.h>

// Per-row least-squares ternary quantization — BIT-EXACT numerics pinned in R13:
//   - exact sort of |w| bits, descending
//   - ReduceWindowRewriter(16) recursive cumsum, trailing pad (R9 association)
//   - score = fl(fl(c*c) * rcp_rn(k)),  v1 = CR divide,  first-occurrence argmax
// This round: bitonic sort (105 passes) -> cub::BlockRadixSort (~7 passes).

#define M_COLS   11008
#define NTHREADS 1024
#define IPT      11
#define NITEMS   (NTHREADS * IPT)   // 11264 >= M_COLS
#define B0       688                // 11008/16
#define B1       43                 // 688/16
#define B2       3                  // ceil(43/16)

using BlockRadixSortT = cub::BlockRadixSort<unsigned int, NTHREADS, IPT>;

// dynamic smem layout (bytes)
static constexpr size_t OFF_SDESC = 0;                         // float[NITEMS]
static constexpr size_t OFF_CS    = OFF_SDESC + NITEMS * 4;    // float[M_COLS]
static constexpr size_t OFF_S0    = OFF_CS + M_COLS * 4;       // float[704]
static constexpr size_t OFF_W1    = OFF_S0 + 704 * 4;          // float[704]
static constexpr size_t OFF_S1    = OFF_W1 + 704 * 4;          // float[48]
static constexpr size_t OFF_W2    = OFF_S1 + 48 * 4;           // float[48]
static constexpr size_t OFF_E2    = OFF_W2 + 48 * 4;           // float[8]
static constexpr size_t OFF_REDS  = OFF_E2 + 8 * 4;            // float[32]
static constexpr size_t OFF_REDJ  = OFF_REDS + 32 * 4;         // int[32]
static constexpr size_t OFF_BC    = OFF_REDJ + 32 * 4;         // float[4]
static constexpr size_t OFF_TEMP  = (OFF_BC + 16 + 127) & ~size_t(127);
static constexpr size_t SMEM_BYTES =
    OFF_TEMP + sizeof(typename BlockRadixSortT::TempStorage);

__global__ __launch_bounds__(NTHREADS)
void lst_ternary_kernel(const float* __restrict__ w,
                        const int* __restrict__ skip_p,
                        float* __restrict__ out,
                        int m)
{
    extern __shared__ unsigned char smem_raw[];
    float* sd   = (float*)(smem_raw + OFF_SDESC);   // sorted descending |w|
    float* cs   = (float*)(smem_raw + OFF_CS);
    float* S0   = (float*)(smem_raw + OFF_S0);
    float* W1   = (float*)(smem_raw + OFF_W1);
    float* S1   = (float*)(smem_raw + OFF_S1);
    float* W2   = (float*)(smem_raw + OFF_W2);
    float* E2   = (float*)(smem_raw + OFF_E2);
    float* reds = (float*)(smem_raw + OFF_REDS);
    int*   redj = (int*)(smem_raw + OFF_REDJ);
    float* bc   = (float*)(smem_raw + OFF_BC);
    typename BlockRadixSortT::TempStorage* temp =
        (typename BlockRadixSortT::TempStorage*)(smem_raw + OFF_TEMP);

    const int tid = threadIdx.x;
    const int row = blockIdx.x;
    const float* wr  = w   + (long long)row * m;
    float*       owr = out + (long long)row * m;

    // ---- 1. load keys = bits of |w| (monotone for nonneg floats) ----
    // striped coalesced load; input arrangement is irrelevant to a sort.
    unsigned int keys[IPT];
    #pragma unroll
    for (int i = 0; i < IPT; ++i) {
        const int idx = i * NTHREADS + tid;
        keys[i] = (idx < m) ? (__float_as_uint(wr[idx]) & 0x7fffffffu) : 0u;
    }

    // ---- 2. exact radix sort, descending (pads=0 land at the tail) ----
    BlockRadixSortT(*temp).SortDescending(keys, 0, 31);
    // blocked output: thread t holds ranks [t*IPT, (t+1)*IPT)
    #pragma unroll
    for (int i = 0; i < IPT; ++i)
        sd[tid * IPT + i] = __uint_as_float(keys[i]);
    __syncthreads();

    // ---- 3. ReduceWindowRewriter(16), recursive, trailing pad (R9 assoc) ----
    // 3a. level0 partials: per-16 fold-left over descending values
    for (int b = tid; b < B0; b += NTHREADS) {
        const int base = b * 16;
        float p = 0.0f;
        #pragma unroll
        for (int r = 0; r < 16; ++r) {
            p = __fadd_rn(p, sd[base + r]);
            cs[base + r] = p;
        }
        S0[b] = p;
    }
    __syncthreads();
    // 3b. level1 partials over S0 (688 = 43*16 exact)
    for (int b = tid; b < B1; b += NTHREADS) {
        const int base = b * 16;
        float p = 0.0f;
        #pragma unroll
        for (int r = 0; r < 16; ++r) {
            p = __fadd_rn(p, S0[base + r]);
            W1[base + r] = p;
        }
        S1[b] = p;
    }
    __syncthreads();
    // 3c. level2 partials over S1 (43 entries, 3 blocks; last block short)
    if (tid < B2) {
        const int base = tid * 16;
        const int hi = (base + 16 < B1) ? base + 16 : B1;
        float p = 0.0f;
        for (int t = base; t < hi; ++t) {
            p = __fadd_rn(p, S1[t]);
            W2[t] = p;
        }
        if (tid == 0) E2[4] = p;            // S2[0]
        if (tid == 1) E2[5] = p;            // S2[1]
    }
    __syncthreads();
    // 3d. base-case exclusive cumsum of S2 -> E2
    if (tid == 0) {
        E2[0] = 0.0f;
        E2[1] = E2[4];                       // S2[0]
        E2[2] = __fadd_rn(E2[4], E2[5]);     // fl(S2[0]+S2[1])
    }
    __syncthreads();
    // 3e. scan1 inclusive (in place over W2): t in [16, 43)
    for (int t = 16 + tid; t < B1; t += NTHREADS)
        W2[t] = __fadd_rn(E2[t >> 4], W2[t]);
    __syncthreads();
    // 3f. scan0 inclusive (in place over W1): q in [16, 688); E1[b1]=W2[b1-1]
    for (int q = 16 + tid; q < B0; q += NTHREADS)
        W1[q] = __fadd_rn(W2[(q >> 4) - 1], W1[q]);
    __syncthreads();
    // 3g. final combine: i in [16, m); E0[b0]=W1[b0-1]
    for (int i = 16 + tid; i < m; i += NTHREADS)
        cs[i] = __fadd_rn(W1[(i >> 4) - 1], cs[i]);
    __syncthreads();

    // ---- 4. candidate scores + first-max argmax (jnp.argmax semantics) ----
    // score = fl(fl(c*c) * rcp_rn(k))  -- jitted-XLA divide-by-constant form
    const int skip = *skip_p;
    const int ncand = (m + skip - 1) / skip;

    float bs = -1.0f;
    int   bj = 0x7fffffff;
    for (int t = tid; t < ncand; t += NTHREADS) {
        const int j = t * skip;
        const float c = cs[j];
        const float kf = (float)(j + 1);
        const float sc = __fmul_rn(__fmul_rn(c, c), __frcp_rn(kf));
        if (sc > bs) { bs = sc; bj = j; }  // per-thread j increases -> first max
    }
    #pragma unroll
    for (int o = 16; o > 0; o >>= 1) {
        float os = __shfl_down_sync(0xffffffffu, bs, o);
        int   oj = __shfl_down_sync(0xffffffffu, bj, o);
        if (os > bs || (os == bs && oj < bj)) { bs = os; bj = oj; }
    }
    if ((tid & 31) == 0) { reds[tid >> 5] = bs; redj[tid >> 5] = bj; }
    __syncthreads();
    if (tid < 32) {
        bs = reds[tid]; bj = redj[tid];
        #pragma unroll
        for (int o = 16; o > 0; o >>= 1) {
            float os = __shfl_down_sync(0xffffffffu, bs, o);
            int   oj = __shfl_down_sync(0xffffffffu, bj, o);
            if (os > bs || (os == bs && oj < bj)) { bs = os; bj = oj; }
        }
        if (tid == 0) {
            const int j = bj;
            bc[0] = __fdiv_rn(cs[j], (float)(j + 1));  // v1: true CR division
            bc[1] = sd[j];                             // thr
        }
    }
    __syncthreads();

    // ---- 5. output: w_q = (|w| >= thr) ? copysign(v1, w) : 0 ----
    const float v1  = bc[0];
    const float thr = bc[1];
    const float4* wr4  = (const float4*)wr;
    float4*       out4 = (float4*)owr;
    const int m4 = m >> 2;
    for (int i = tid; i < m4; i += NTHREADS) {
        float4 v = wr4[i];
        float4 o;
        o.x = (fabsf(v.x) >= thr) ? copysignf(v1, v.x) : 0.0f;
        o.y = (fabsf(v.y) >= thr) ? copysignf(v1, v.y) : 0.0f;
        o.z = (fabsf(v.z) >= thr) ? copysignf(v1, v.z) : 0.0f;
        o.w = (fabsf(v.w) >= thr) ? copysignf(v1, v.w) : 0.0f;
        out4[i] = o;
    }
}

extern "C" void kernel_launch(void* const* d_in, const int* in_sizes, int n_in,
                              void* d_out, int out_size)
{
    const float* w      = (const float*)d_in[0];
    const int*   skip_p = (const int*)d_in[1];
    float*       out    = (float*)d_out;

    const int m    = M_COLS;
    const int rows = in_sizes[0] / m;

    cudaFuncSetAttribute(lst_ternary_kernel,
                         cudaFuncAttributeMaxDynamicSharedMemorySize,
                         (int)SMEM_BYTES);

    lst_ternary_kernel<<<rows, NTHREADS, SMEM_BYTES>>>(w, skip_p, out, m);
}